// round 14
// baseline (speedup 1.0000x reference)
#include <cuda_runtime.h>
#include <math.h>

#define NELEM  16384
#define KSEL   8192
#define NC     16
#define NT     1024
#define NW     (NT / 32)
#define NBINS  16384
#define BPT    (NBINS / NT)     // 16 bins per thread
#define SH     12
#define LOBITS 0x3B800000u      // float bits of 2^-8; lower scores clamp to bin 0

// ---- persistent scratch (zero-init at load; maintained across graph replays) ----
// hist + boundary counters double-buffered by launch parity: launch L uses [p=L&1],
// zeroes [p^1] during phase A (its previous reader finished at the launch boundary).
__device__ __align__(16) unsigned int g_hist[2][NBINS];
__device__ __align__(16) uint2 g_cand[NELEM + 8];   // +8: sentinel-safe batch reads
__device__ unsigned int g_ticket[2];
__device__ unsigned int g_done[2];
__device__ unsigned int g_launch;   // monotonic launch ticket (parity + barrier target)
__device__ unsigned int g_arrive;   // monotonic arrival counter (+NC per launch)

__device__ __forceinline__ unsigned int ld_acq(const unsigned int* p) {
    unsigned int v;
    asm volatile("ld.acquire.gpu.u32 %0, [%1];" : "=r"(v) : "l"(p) : "memory");
    return v;
}
__device__ __forceinline__ void red_rel_add(unsigned int* p, unsigned int v) {
    asm volatile("red.release.gpu.global.add.u32 [%0], %1;" :: "l"(p), "r"(v) : "memory");
}
__device__ __forceinline__ int score_bin(unsigned int v) {
    const int d = (int)(v - LOBITS);
    int bin = d < 0 ? 0 : (d >> SH);
    return bin < NBINS - 1 ? bin : NBINS - 1;
}

__global__ __launch_bounds__(NT, 1)
void connect_attention_b(const float* __restrict__ x,
                         const float* __restrict__ w7,
                         float* __restrict__ out)
{
    __shared__ float        sx[NT + 6];
    __shared__ float        swt[7];
    __shared__ unsigned int sm_w[NW];
    __shared__ unsigned int s_tick, s_w0, s_w1;

    const int tid  = threadIdx.x;
    const int lane = tid & 31;
    const int wid  = tid >> 5;
    const int E0   = (int)blockIdx.x * NT;
    const int gid  = E0 + tid;

    if (tid == 0) s_tick = atomicAdd(&g_launch, 1u);
    if (tid < 7)  swt[tid] = __ldg(w7 + tid);

    // ---- stage x tile (+3 halo each side) ----
    sx[3 + tid] = __ldg(x + gid);
    if (tid < 3) {
        const int gl = E0 - 3 + tid;
        sx[tid] = (gl >= 0) ? __ldg(x + gl) : 0.0f;
        const int gr = E0 + NT + tid;
        sx[3 + NT + tid] = (gr < NELEM) ? __ldg(x + gr) : 0.0f;
    }
    __syncthreads();

    const unsigned int L   = s_tick / NC;     // launch index (all CTAs agree)
    const unsigned int par = L & 1u;

    // ---- conv 'same' + sigmoid (accurate expf: protects selection boundary) ----
    const float xi = sx[3 + tid];
    float y = sx[tid] * swt[0];
    y = fmaf(sx[tid + 1], swt[1], y);
    y = fmaf(sx[tid + 2], swt[2], y);
    y = fmaf(xi,          swt[3], y);
    y = fmaf(sx[tid + 4], swt[4], y);
    y = fmaf(sx[tid + 5], swt[5], y);
    y = fmaf(sx[tid + 6], swt[6], y);
    const float s = 1.0f / (1.0f + expf(-y));
    out[NELEM + gid] = s;                           // attention_score output

    const unsigned int v = __float_as_uint(s);      // positive: bit order == value order
    const int bin = score_bin(v);
    atomicAdd(&g_hist[par][bin], 1u);               // spread REDs

    // prepare NEXT launch's buffers (untouched during this launch)
    g_hist[par ^ 1u][gid] = 0u;                     // 16384 threads cover all bins
    if (gid == 0) { g_ticket[par ^ 1u] = 0u; g_done[par ^ 1u] = 0u; }

    // ---- single grid sync: 16 release-RMWs + acquire-READ polling ----
    __syncthreads();
    if (tid == 0) {
        __threadfence();                             // publish this CTA's REDs
        red_rel_add(&g_arrive, 1u);
        const unsigned int target = (unsigned int)NC * (L + 1u);
        while (ld_acq(&g_arrive) < target) __nanosleep(64);
    }
    __syncthreads();

    // ---- redundant per-CTA scan: 16 bins/thread, register resident ----
    const unsigned int* hist = g_hist[par];
    unsigned int h[BPT];
    {
        const uint4* hp = (const uint4*)(hist + tid * BPT);
        const uint4 q0 = __ldcg(hp + 0), q1 = __ldcg(hp + 1),
                    q2 = __ldcg(hp + 2), q3 = __ldcg(hp + 3);
        h[0]=q0.x;  h[1]=q0.y;  h[2]=q0.z;  h[3]=q0.w;
        h[4]=q1.x;  h[5]=q1.y;  h[6]=q1.z;  h[7]=q1.w;
        h[8]=q2.x;  h[9]=q2.y;  h[10]=q2.z; h[11]=q2.w;
        h[12]=q3.x; h[13]=q3.y; h[14]=q3.z; h[15]=q3.w;
    }
    unsigned int local = 0;
    #pragma unroll
    for (int q = 0; q < BPT; ++q) local += h[q];

    // block exclusive scan (32 warps; all 32 lanes active in every shuffle)
    unsigned int inc = local;
    #pragma unroll
    for (int o = 1; o < 32; o <<= 1) {
        unsigned int t = __shfl_up_sync(0xffffffffu, inc, o);
        if (lane >= o) inc += t;
    }
    if (lane == 31) sm_w[wid] = inc;
    __syncthreads();
    if (wid == 0) {
        unsigned int wsum = sm_w[lane];              // NW == 32
        unsigned int winc = wsum;
        #pragma unroll
        for (int o = 1; o < 32; o <<= 1) {
            unsigned int t = __shfl_up_sync(0xffffffffu, winc, o);
            if (lane >= o) winc += t;
        }
        sm_w[lane] = winc - wsum;                    // exclusive warp base
    }
    __syncthreads();
    const unsigned int base = sm_w[wid] + inc - local;

    if (base < KSEL && base + local >= KSEL) {       // exactly one thread; regs only
        unsigned int c = base;
        #pragma unroll
        for (int q = 0; q < BPT; ++q) {
            if (c + h[q] >= KSEL) {
                s_w0 = (unsigned)(tid * BPT + q) | ((KSEL - c) << 16);  // bstar|jkeep<<16
                s_w1 = h[q];                                             // hcount
                break;
            }
            c += h[q];
        }
    }
    __syncthreads();
    const int          bstar  = (int)(s_w0 & 0xFFFFu);
    const unsigned int jkeep  = s_w0 >> 16;
    const unsigned int hcount = s_w1;

    // ---- emit from register-held x, s ----
    if (bin != bstar) {
        out[gid] = (bin < bstar) ? xi * (s + 1.0f) : 0.0f;
    } else {
        // register, release, wait for all hcount registrants, exact stable rank
        const unsigned int t = atomicAdd(&g_ticket[par], 1u);
        g_cand[t] = make_uint2(v, (unsigned int)gid);
        red_rel_add(&g_done[par], 1u);

        bool full = true;
        unsigned int spins = 0;
        while (ld_acq(&g_done[par]) < hcount) {
            __nanosleep(32);
            if (++spins > (1u << 18)) { full = false; break; }   // safety valve
        }

        unsigned int rank = 0;
        if (full) {
            // BATCHED candidate reads: 8 independent loads per chunk (MLP=8)
            // instead of a serial hcount-long L2 latency chain.
            for (unsigned int c = 0; c < hcount; c += 8) {
                uint2 cd[8];
                #pragma unroll
                for (int j = 0; j < 8; ++j) {
                    // sentinel pad: g_cand has +8 slack; out-of-range entries are
                    // masked below (predicated loads stay independent)
                    cd[j] = (c + (unsigned)j < hcount)
                          ? __ldcg(&g_cand[c + j])
                          : make_uint2(0xFFFFFFFFu, 0xFFFFFFFFu);
                }
                #pragma unroll
                for (int j = 0; j < 8; ++j)
                    rank += (cd[j].x < v) || (cd[j].x == v && cd[j].y < (unsigned)gid);
            }
        } else {
            // fallback: exact rank from the stored score array (same result),
            // batched 8-wide for MLP
            for (int j0 = 0; j0 < NELEM; j0 += 8) {
                unsigned int vj[8];
                #pragma unroll
                for (int j = 0; j < 8; ++j)
                    vj[j] = __float_as_uint(out[NELEM + j0 + j]);
                #pragma unroll
                for (int j = 0; j < 8; ++j) {
                    if (score_bin(vj[j]) == bstar)
                        rank += (vj[j] < v) || (vj[j] == v && (j0 + j) < gid);
                }
            }
        }
        out[gid] = (rank < jkeep) ? xi * (s + 1.0f) : 0.0f;
    }
}

extern "C" void kernel_launch(void* const* d_in, const int* in_sizes, int n_in,
                              void* d_out, int out_size)
{
    const float* x = (const float*)d_in[0];
    const float* w = (const float*)d_in[1];
    if (n_in >= 2 && in_sizes[0] == 7) {   // defensive input-order check
        const float* t = x; x = w; w = t;
    }
    float* out = (float*)d_out;

    connect_attention_b<<<NC, NT>>>(x, w, out);
}

// round 15
// speedup vs baseline: 1.3170x; 1.3170x over previous
#include <cuda_runtime.h>
#include <math.h>

#define NELEM   16384
#define KSEL    8192
#define NB      8        // CTAs == cluster size (one CGA spans the grid)
#define NT      1024
#define CPB     2048     // contiguous elements per CTA
#define NBINS   16384
#define SH      12
#define LOBITS  0x3B800000u   // float bits of 2^-8; lower scores clamp to bin 0
#define CANDMAX 192

// ---- persistent scratch (zero-init at load; maintained across graph replays) ----
__device__ __align__(16) unsigned int g_hist[NBINS];   // re-zeroed post-cbar2 each run
__device__ uint2        g_cand[NELEM];                 // fallback path only
__device__ unsigned int g_ccount;                      // fallback ticket (reset pre-bar1)

// HW cluster barrier; arrive has cluster-scope release semantics (covers both
// gmem writes and shared::cluster stores by cluster threads).
__device__ __forceinline__ void cbar()
{
    asm volatile("barrier.cluster.arrive.aligned;" ::: "memory");
    asm volatile("barrier.cluster.wait.aligned;"   ::: "memory");
}
__device__ __forceinline__ unsigned int ctarank()
{
    unsigned int r;
    asm("mov.u32 %0, %%cluster_ctarank;" : "=r"(r));
    return r;
}
__device__ __forceinline__ unsigned int mapa0(unsigned int a)   // addr in rank 0
{
    unsigned int r;
    asm("mapa.shared::cluster.u32 %0, %1, %2;" : "=r"(r) : "r"(a), "r"(0));
    return r;
}
__device__ __forceinline__ unsigned int dsmem_ticket(unsigned int addr)
{
    unsigned int old;
    asm volatile("atom.relaxed.cluster.shared::cluster.add.u32 %0, [%1], %2;"
                 : "=r"(old) : "r"(addr), "r"(1u) : "memory");
    return old;
}
__device__ __forceinline__ void dsmem_st2(unsigned int addr, unsigned int a, unsigned int b)
{
    asm volatile("st.shared::cluster.v2.u32 [%0], {%1, %2};"
                 :: "r"(addr), "r"(a), "r"(b) : "memory");
}
__device__ __forceinline__ uint2 dsmem_ld2(unsigned int addr)
{
    uint2 r;
    asm volatile("ld.shared::cluster.v2.u32 {%0, %1}, [%2];"
                 : "=r"(r.x), "=r"(r.y) : "r"(addr));
    return r;
}
__device__ __forceinline__ void dsmem_ack(unsigned int addr, unsigned int n)
{
    asm volatile("red.relaxed.cluster.shared::cluster.add.u32 [%0], %1;"
                 :: "r"(addr), "r"(n) : "memory");
}

__global__ __launch_bounds__(NT, 1) __cluster_dims__(NB, 1, 1)
void connect_attention_cga4(const float* __restrict__ x,
                            const float* __restrict__ w7,
                            float* __restrict__ out)
{
    __shared__ float        sx[CPB + 6];     // x[E0-3 .. E0+CPB+2]
    __shared__ float        swt[7];
    __shared__ unsigned int sm_w[32];
    __shared__ unsigned int s_w0, s_w1;
    __shared__ __align__(8) uint2 s_cand[CANDMAX];   // used in rank 0 only
    __shared__ unsigned int s_cnt;
    __shared__ volatile unsigned int s_ack;

    const int tid  = threadIdx.x;
    const int lane = tid & 31;
    const int wid  = tid >> 5;
    const int E0   = (int)blockIdx.x * CPB;
    const int l0   = 2 * tid;
    const int e0   = E0 + l0;
    const unsigned int rank = ctarank();

    if (tid == 0) { s_cnt = 0u; s_ack = 0u; }
    if (e0 == 0)  g_ccount = 0u;              // fallback ticket; ordered by cbar1
    if (tid < 7)  swt[tid] = __ldg(w7 + tid);

    // ---- stage x tile (+halo) into smem ----
    {
        const float2 xv = *(const float2*)(x + e0);
        sx[3 + l0]     = xv.x;
        sx[3 + l0 + 1] = xv.y;
        if (tid < 3) {
            const int gl = E0 - 3 + tid;
            sx[tid] = (gl >= 0) ? __ldg(x + gl) : 0.0f;
            const int gr = E0 + CPB + tid;
            sx[3 + CPB + tid] = (gr < NELEM) ? __ldg(x + gr) : 0.0f;
        }
    }
    __syncthreads();

    // DSMEM addresses of rank 0's candidate structures
    const unsigned int cand0 = mapa0((unsigned int)__cvta_generic_to_shared(s_cand));
    const unsigned int cnt0  = mapa0((unsigned int)__cvta_generic_to_shared((void*)&s_cnt));
    const unsigned int ack0  = mapa0((unsigned int)__cvta_generic_to_shared((void*)&s_ack));

    const float w0 = swt[0], w1 = swt[1], w2 = swt[2], w3 = swt[3],
                w4 = swt[4], w5 = swt[5], w6 = swt[6];

    // ---- conv 'same' + sigmoid for elems e0, e0+1 ----
    const float a0 = sx[l0],     a1 = sx[l0 + 1], a2 = sx[l0 + 2], a3 = sx[l0 + 3],
                a4 = sx[l0 + 4], a5 = sx[l0 + 5], a6 = sx[l0 + 6], a7 = sx[l0 + 7];

    float y0 = a0 * w0;
    y0 = fmaf(a1, w1, y0); y0 = fmaf(a2, w2, y0); y0 = fmaf(a3, w3, y0);
    y0 = fmaf(a4, w4, y0); y0 = fmaf(a5, w5, y0); y0 = fmaf(a6, w6, y0);
    float y1 = a1 * w0;
    y1 = fmaf(a2, w1, y1); y1 = fmaf(a3, w2, y1); y1 = fmaf(a4, w3, y1);
    y1 = fmaf(a5, w4, y1); y1 = fmaf(a6, w5, y1); y1 = fmaf(a7, w6, y1);

    const float s0 = 1.0f / (1.0f + expf(-y0));
    const float s1 = 1.0f / (1.0f + expf(-y1));
    *(float2*)(out + NELEM + e0) = make_float2(s0, s1);   // attention_score

    const unsigned int v0 = __float_as_uint(s0);   // positive: bit order == value order
    const unsigned int v1 = __float_as_uint(s1);
    const int d0 = (int)(v0 - LOBITS);
    const int d1 = (int)(v1 - LOBITS);
    const int bin0 = d0 < 0 ? 0 : (d0 >> SH);      // < NBINS (s < 1.0)
    const int bin1 = d1 < 0 ? 0 : (d1 >> SH);

    if (bin0 == bin1) {
        atomicAdd(&g_hist[bin0], 2u);
    } else {
        atomicAdd(&g_hist[bin0], 1u);
        atomicAdd(&g_hist[bin1], 1u);
    }

    cbar();   // ---- bar1: histogram complete ----

    // ---- redundant per-CTA prefix scan over 16384 bins (16/thread, registers) ----
    {
        unsigned int h[16];
        {
            const uint4* hp = (const uint4*)(g_hist + tid * 16);
            uint4 q0 = __ldcg(hp + 0), q1 = __ldcg(hp + 1),
                  q2 = __ldcg(hp + 2), q3 = __ldcg(hp + 3);
            h[0]=q0.x;  h[1]=q0.y;  h[2]=q0.z;  h[3]=q0.w;
            h[4]=q1.x;  h[5]=q1.y;  h[6]=q1.z;  h[7]=q1.w;
            h[8]=q2.x;  h[9]=q2.y;  h[10]=q2.z; h[11]=q2.w;
            h[12]=q3.x; h[13]=q3.y; h[14]=q3.z; h[15]=q3.w;
        }
        unsigned int local = 0;
        #pragma unroll
        for (int q = 0; q < 16; ++q) local += h[q];

        unsigned int inc = local;
        #pragma unroll
        for (int o = 1; o < 32; o <<= 1) {
            unsigned int t = __shfl_up_sync(0xffffffffu, inc, o);
            if (lane >= o) inc += t;
        }
        if (lane == 31) sm_w[wid] = inc;
        __syncthreads();
        if (wid == 0) {
            unsigned int wsum = sm_w[lane];
            unsigned int winc = wsum;
            #pragma unroll
            for (int o = 1; o < 32; o <<= 1) {
                unsigned int t = __shfl_up_sync(0xffffffffu, winc, o);
                if (lane >= o) winc += t;
            }
            sm_w[lane] = winc - wsum;    // exclusive warp base
        }
        __syncthreads();
        const unsigned int base = sm_w[wid] + inc - local;

        if (base < KSEL && base + local >= KSEL) {   // exactly one thread
            unsigned int c = base;
            #pragma unroll
            for (int q = 0; q < 16; ++q) {
                if (c + h[q] >= KSEL) {
                    s_w0 = (unsigned)(tid * 16 + q) | ((KSEL - c) << 16);  // bstar|jkeep<<16
                    s_w1 = h[q];                                            // hcount
                    break;
                }
                c += h[q];
            }
        }
    }
    __syncthreads();
    const int          bstar  = (int)(s_w0 & 0xFFFFu);
    const unsigned int jkeep  = s_w0 >> 16;
    const unsigned int hcount = s_w1;
    const bool         fast   = (hcount <= CANDMAX);

    // ---- register boundary candidates: DSMEM fast path / gmem fallback ----
    const bool b0 = (bin0 == bstar);
    const bool b1 = (bin1 == bstar);
    if (b0) {
        if (fast) { const unsigned int t = dsmem_ticket(cnt0); dsmem_st2(cand0 + t * 8u, v0, (unsigned)e0); }
        else      { const unsigned int t = atomicAdd(&g_ccount, 1u); g_cand[t] = make_uint2(v0, (unsigned)e0); }
    }
    if (b1) {
        if (fast) { const unsigned int t = dsmem_ticket(cnt0); dsmem_st2(cand0 + t * 8u, v1, (unsigned)(e0 + 1)); }
        else      { const unsigned int t = atomicAdd(&g_ccount, 1u); g_cand[t] = make_uint2(v1, (unsigned)(e0 + 1)); }
    }

    cbar();   // ---- bar2: candidates visible everywhere ----

    // hist re-zero for next replay (all reads finished at bar2)
    ((uint2*)(g_hist + (int)blockIdx.x * (NBINS / NB)))[tid] = make_uint2(0u, 0u);

    // ---- exact stable rank among candidates + emit new_x ----
    float o0 = (bin0 < bstar) ? a3 * (s0 + 1.0f) : 0.0f;   // a3 == x[e0]
    float o1 = (bin1 < bstar) ? a4 * (s1 + 1.0f) : 0.0f;   // a4 == x[e0+1]

    if (b0 | b1) {
        unsigned int r0 = 0, r1 = 0;
        for (unsigned int c = 0; c < hcount; c += 4) {     // 4 independent loads/iter
            uint2 cd[4];
            #pragma unroll
            for (int j = 0; j < 4; ++j) {
                const unsigned int idx = (c + (unsigned)j < hcount) ? c + (unsigned)j : 0u;
                cd[j] = fast ? dsmem_ld2(cand0 + idx * 8u) : __ldcg(&g_cand[idx]);
            }
            #pragma unroll
            for (int j = 0; j < 4; ++j) {
                if (c + (unsigned)j < hcount) {
                    r0 += (cd[j].x < v0) || (cd[j].x == v0 && cd[j].y < (unsigned)e0);
                    r1 += (cd[j].x < v1) || (cd[j].x == v1 && cd[j].y < (unsigned)(e0 + 1));
                }
            }
        }
        if (b0) o0 = (r0 < jkeep) ? a3 * (s0 + 1.0f) : 0.0f;
        if (b1) o1 = (r1 < jkeep) ? a4 * (s1 + 1.0f) : 0.0f;
    }
    *(float2*)(out + e0) = make_float2(o0, o1);

    // readers ack after their last DSMEM read; rank 0 stays alive until all acked
    if (fast && (b0 | b1)) dsmem_ack(ack0, (unsigned)b0 + (unsigned)b1);
    if (fast && rank == 0 && tid == 0) {
        while (s_ack < hcount) { }     // local smem poll (~cheap), bounded by bar2
    }
}

extern "C" void kernel_launch(void* const* d_in, const int* in_sizes, int n_in,
                              void* d_out, int out_size)
{
    const float* x = (const float*)d_in[0];
    const float* w = (const float*)d_in[1];
    if (n_in >= 2 && in_sizes[0] == 7) {   // defensive input-order check
        const float* t = x; x = w; w = t;
    }
    float* out = (float*)d_out;

    connect_attention_cga4<<<NB, NT>>>(x, w, out);
}